// round 13
// baseline (speedup 1.0000x reference)
#include <cuda_runtime.h>
#include <cuda_bf16.h>
#include <cstdint>

#define NN 50000
#define EE 800000
#define GG 64
#define HH 64
#define NB ((NN + 255) / 256)   // 196 scan chunks

// ---------------- scratch (device globals; no allocation allowed) ----------
__device__ __align__(16) int   g_degin_i[NN];
__device__ __align__(16) int   g_degout_i[NN];
__device__ __align__(16) int   g_rowptr[NN + 1];
__device__ __align__(16) int   g_cursor[NN];
__device__ __align__(16) int   g_blocksum[NB];
__device__ __align__(16) int   g_csr_src[EE];
__device__ __align__(16) float g_norm_src[NN];
__device__ __align__(16) float g_norm_dst[NN];
__device__ __align__(16) float g_hA[NN * HH];     // feature ping buffer
__device__ __align__(16) float g_hB[NN * HH];     // feature pong buffer
__device__ __align__(16) float g_agg1[NN * 4];    // layer-1 aggregation (4-wide)
__device__ __align__(16) float g_gsum[GG * HH];   // graph pooling sums
__device__ __align__(16) float g_gcnt[GG];

// grid barrier state: count returns to 0 after each use, phase is monotonic,
// waits are RELATIVE to the phase read at kernel entry -> graph-replay safe.
__device__ unsigned g_bar_count;
__device__ volatile unsigned g_bar_phase;

// ---------------- helpers ---------------------------------------------------
__device__ __forceinline__ void red4(float* p, float4 v) {
    asm volatile("red.global.add.v4.f32 [%0], {%1, %2, %3, %4};"
                 :: "l"(p), "f"(v.x), "f"(v.y), "f"(v.z), "f"(v.w) : "memory");
}

// grid-wide barrier: all gridDim.x blocks must be co-resident.
__device__ __forceinline__ void grid_sync(unsigned target) {
    __syncthreads();
    if (threadIdx.x == 0) {
        __threadfence();
        unsigned old = atomicAdd(&g_bar_count, 1u);
        if (old == gridDim.x - 1u) {
            atomicExch(&g_bar_count, 0u);
            __threadfence();
            g_bar_phase = target;              // release
        } else {
            while (g_bar_phase < target) { }   // spin
        }
        __threadfence();                        // acquire
    }
    __syncthreads();
}

// ---------------- persistent prep kernel (CSR build + layer 1) ----------------
__global__ void __launch_bounds__(256) prep_kernel(
        const int* __restrict__ src, const int* __restrict__ dst,
        const int* __restrict__ gids,
        const float* __restrict__ W1, const float* __restrict__ b1) {
    __shared__ int s_scan[256];

    const int tid = threadIdx.x;
    const int bid = blockIdx.x;
    const int nb = gridDim.x;
    const int gsz = nb * 256;
    const int idx = bid * 256 + tid;

    unsigned bar0 = 0;
    if (tid == 0) bar0 = g_bar_phase;

    // P0: zero degrees + pooling buffers
    for (int i = idx; i < NN; i += gsz) { g_degin_i[i] = 0; g_degout_i[i] = 0; }
    for (int i = idx; i < GG * HH; i += gsz) g_gsum[i] = 0.f;
    for (int i = idx; i < GG; i += gsz) g_gcnt[i] = 0.f;
    grid_sync(bar0 + 1);

    // P1: degree histogram
    for (int e = idx; e < EE; e += gsz) {
        atomicAdd(&g_degin_i[dst[e]], 1);
        atomicAdd(&g_degout_i[src[e]], 1);
    }
    grid_sync(bar0 + 2);

    // P2: per-chunk exclusive scan (grid-stride over chunks)
    for (int c = bid; c < NB; c += nb) {
        int n = c * 256 + tid;
        int v = (n < NN) ? g_degin_i[n] : 0;
        s_scan[tid] = v;
        __syncthreads();
#pragma unroll
        for (int off = 1; off < 256; off <<= 1) {
            int add = (tid >= off) ? s_scan[tid - off] : 0;
            __syncthreads();
            s_scan[tid] += add;
            __syncthreads();
        }
        if (n < NN) g_rowptr[n] = s_scan[tid] - v;
        if (tid == 255) g_blocksum[c] = s_scan[255];
        __syncthreads();
    }
    grid_sync(bar0 + 3);

    // P3: scan of chunk sums (block 0)
    if (bid == 0) {
        int v = (tid < NB) ? g_blocksum[tid] : 0;
        s_scan[tid] = v;
        __syncthreads();
#pragma unroll
        for (int off = 1; off < 256; off <<= 1) {
            int add = (tid >= off) ? s_scan[tid - off] : 0;
            __syncthreads();
            s_scan[tid] += add;
            __syncthreads();
        }
        if (tid < NB) g_blocksum[tid] = s_scan[tid] - v;
        if (tid == 0) g_rowptr[NN] = EE;
    }
    grid_sync(bar0 + 4);

    // P4: finalize rowptr/cursors + features/norms
    for (int n = idx; n < NN; n += gsz) {
        int r = g_rowptr[n] + g_blocksum[n >> 8];
        g_rowptr[n] = r;
        g_cursor[n] = r;
        float di = (float)g_degin_i[n];
        float dout = (float)g_degout_i[n];
        float h1 = di;
        float h2 = (di - 3.f > 0.f) ? 1.f : 0.f;
        float h3 = 3.f / di;
        float h4 = (di - 4.f > 0.f) ? 1.f : 0.f;
        float ns = rsqrtf(fmaxf(dout, 1.f));
        float nd = rsqrtf(fmaxf(di, 1.f));
        g_norm_src[n] = ns;
        g_norm_dst[n] = nd;
        reinterpret_cast<float4*>(g_hA)[n] =
            make_float4(h1 * ns, h2 * ns, h3 * ns, h4 * ns);
        atomicAdd(&g_gcnt[gids[n]], 1.f);
    }
    grid_sync(bar0 + 5);

    // P5: scatter edges into CSR
    for (int e = idx; e < EE; e += gsz) {
        int d = dst[e];
        int pos = atomicAdd(&g_cursor[d], 1);
        g_csr_src[pos] = src[e];
    }
    grid_sync(bar0 + 6);

    // P6: layer-1 aggregation (4-wide)
    for (int n = idx; n < NN; n += gsz) {
        int e0 = g_rowptr[n], e1 = g_rowptr[n + 1];
        const float4* h4 = reinterpret_cast<const float4*>(g_hA);
        float4 acc = make_float4(0.f, 0.f, 0.f, 0.f);
        int e = e0;
        for (; e + 1 < e1; e += 2) {
            float4 v0 = h4[g_csr_src[e]];
            float4 v1 = h4[g_csr_src[e + 1]];
            acc.x += v0.x + v1.x; acc.y += v0.y + v1.y;
            acc.z += v0.z + v1.z; acc.w += v0.w + v1.w;
        }
        if (e < e1) {
            float4 v = h4[g_csr_src[e]];
            acc.x += v.x; acc.y += v.y; acc.z += v.z; acc.w += v.w;
        }
        reinterpret_cast<float4*>(g_agg1)[n] = acc;
    }
    grid_sync(bar0 + 7);

    // P7: layer-1 node update -> g_hA (64-wide)
    for (int t = idx; t < NN * HH; t += gsz) {
        int n = t >> 6;
        int o = t & 63;
        float nd = g_norm_dst[n];
        float ns = g_norm_src[n];
        float4 x = reinterpret_cast<const float4*>(g_agg1)[n];
        float acc = b1[o];
        acc = fmaf(x.x * nd, W1[0 * HH + o], acc);
        acc = fmaf(x.y * nd, W1[1 * HH + o], acc);
        acc = fmaf(x.z * nd, W1[2 * HH + o], acc);
        acc = fmaf(x.w * nd, W1[3 * HH + o], acc);
        acc = fmaxf(acc, 0.f) * ns;
        g_hA[t] = acc;
    }
}

// ---------------- fused layers 2..4 (R8 champion body) ------------------------
// One warp = 4 nodes. LAST additionally does grid barrier + fused output head.
template <bool LAST>
__global__ void __launch_bounds__(256) layer_kernel(
        const float* __restrict__ hin, float* __restrict__ hout,
        const float* __restrict__ W, const float* __restrict__ b,
        const int* __restrict__ graph_ids,
        const float* __restrict__ Wout, const float* __restrict__ bout,
        float* __restrict__ out) {
    __shared__ float Ws[HH * HH];
    __shared__ float bs[HH];
    __shared__ float xs[8][4][68];   // [warp][node-in-quad][64+pad]

    int tid = threadIdx.x;
    float4* Ws4 = reinterpret_cast<float4*>(Ws);
    const float4* Wg4 = reinterpret_cast<const float4*>(W);
    for (int i = tid; i < HH * HH / 4; i += 256) Ws4[i] = Wg4[i];
    if (tid < HH) bs[tid] = b[tid];

    unsigned bar0 = 0;
    if (LAST && tid == 0) bar0 = g_bar_phase;
    __syncthreads();

    int warp = tid >> 5;
    int lane = tid & 31;
    int half = lane >> 4;      // 0 or 1
    int o4 = lane & 15;        // float4 slice

    const float4* h4 = reinterpret_cast<const float4*>(hin);
    const int* __restrict__ csr = g_csr_src;

    const int NQ = NN / 4;     // 12500 quads

    for (int quad = blockIdx.x * 8 + warp; quad < NQ; quad += gridDim.x * 8) {
        // ---- gather: this lane handles nodes (half) and (half+2) of the quad
#pragma unroll
        for (int g = 0; g < 2; g++) {
            int q = half + 2 * g;
            int n = quad * 4 + q;
            int e0 = g_rowptr[n], e1 = g_rowptr[n + 1];
            float4 acc = make_float4(0.f, 0.f, 0.f, 0.f);
            int e = e0;
            for (; e + 3 < e1; e += 4) {
                int s0 = csr[e], s1 = csr[e + 1], s2 = csr[e + 2], s3 = csr[e + 3];
                float4 v0 = h4[s0 * 16 + o4];
                float4 v1 = h4[s1 * 16 + o4];
                float4 v2 = h4[s2 * 16 + o4];
                float4 v3 = h4[s3 * 16 + o4];
                acc.x += (v0.x + v1.x) + (v2.x + v3.x);
                acc.y += (v0.y + v1.y) + (v2.y + v3.y);
                acc.z += (v0.z + v1.z) + (v2.z + v3.z);
                acc.w += (v0.w + v1.w) + (v2.w + v3.w);
            }
            for (; e < e1; e++) {
                float4 v = h4[csr[e] * 16 + o4];
                acc.x += v.x; acc.y += v.y; acc.z += v.z; acc.w += v.w;
            }
            float nd = g_norm_dst[n];
            acc.x *= nd; acc.y *= nd; acc.z *= nd; acc.w *= nd;
            reinterpret_cast<float4*>(&xs[warp][q][0])[o4] = acc;
        }
        __syncwarp();
        // ---- GEMM: slice o4 for nodes q0=2*half, q1=2*half+1 (shared W loads)
        {
            int q0 = 2 * half;
            int n0 = quad * 4 + q0;
            int n1 = n0 + 1;
            float4 bb = reinterpret_cast<float4*>(bs)[o4];
            float4 r0 = bb, r1 = bb;
            const float4* x0row = reinterpret_cast<const float4*>(&xs[warp][q0][0]);
            const float4* x1row = reinterpret_cast<const float4*>(&xs[warp][q0 + 1][0]);
#pragma unroll
            for (int k4 = 0; k4 < 16; k4++) {
                float4 x0v = x0row[k4];
                float4 x1v = x1row[k4];
#pragma unroll
                for (int j = 0; j < 4; j++) {
                    float4 w = Ws4[(k4 * 4 + j) * 16 + o4];
                    float a = (j == 0) ? x0v.x : (j == 1) ? x0v.y : (j == 2) ? x0v.z : x0v.w;
                    float c = (j == 0) ? x1v.x : (j == 1) ? x1v.y : (j == 2) ? x1v.z : x1v.w;
                    r0.x = fmaf(a, w.x, r0.x);
                    r0.y = fmaf(a, w.y, r0.y);
                    r0.z = fmaf(a, w.z, r0.z);
                    r0.w = fmaf(a, w.w, r0.w);
                    r1.x = fmaf(c, w.x, r1.x);
                    r1.y = fmaf(c, w.y, r1.y);
                    r1.z = fmaf(c, w.z, r1.z);
                    r1.w = fmaf(c, w.w, r1.w);
                }
            }
            r0.x = fmaxf(r0.x, 0.f); r0.y = fmaxf(r0.y, 0.f);
            r0.z = fmaxf(r0.z, 0.f); r0.w = fmaxf(r0.w, 0.f);
            r1.x = fmaxf(r1.x, 0.f); r1.y = fmaxf(r1.y, 0.f);
            r1.z = fmaxf(r1.z, 0.f); r1.w = fmaxf(r1.w, 0.f);
            if (!LAST) {
                float ns0 = g_norm_src[n0];
                float ns1 = g_norm_src[n1];
                r0.x *= ns0; r0.y *= ns0; r0.z *= ns0; r0.w *= ns0;
                r1.x *= ns1; r1.y *= ns1; r1.z *= ns1; r1.w *= ns1;
                reinterpret_cast<float4*>(hout)[n0 * 16 + o4] = r0;
                reinterpret_cast<float4*>(hout)[n1 * 16 + o4] = r1;
            } else {
                int g0 = graph_ids[n0];
                int g1 = graph_ids[n1];
                red4(&g_gsum[g0 * HH + o4 * 4], r0);
                red4(&g_gsum[g1 * HH + o4 * 4], r1);
            }
        }
        __syncwarp();
    }

    if (LAST) {
        grid_sync(bar0 + 1);   // pooling complete across the grid
        if (blockIdx.x < GG) {
            int g = blockIdx.x;
            if (tid < HH)
                bs[tid] = g_gsum[g * HH + tid] * (1.f / g_gcnt[g]) * Wout[tid];
            __syncthreads();
            if (tid < 32) {
                float x = bs[tid] + bs[tid + 32];
#pragma unroll
                for (int off = 16; off > 0; off >>= 1)
                    x += __shfl_xor_sync(0xFFFFFFFF, x, off);
                if (tid == 0) out[g] = 1.f / (1.f + expf(-(x + bout[0])));
            }
        }
    }
}

// ---------------- launch -----------------------------------------------------
extern "C" void kernel_launch(void* const* d_in, const int* in_sizes, int n_in,
                              void* d_out, int out_size) {
    const int*   src  = (const int*)d_in[0];
    const int*   dst  = (const int*)d_in[1];
    const int*   gids = (const int*)d_in[2];
    const float* W1   = (const float*)d_in[3];
    const float* b1   = (const float*)d_in[4];
    const float* W2   = (const float*)d_in[5];
    const float* b2   = (const float*)d_in[6];
    const float* W3   = (const float*)d_in[7];
    const float* b3   = (const float*)d_in[8];
    const float* W4   = (const float*)d_in[9];
    const float* b4   = (const float*)d_in[10];
    const float* Wout = (const float*)d_in[11];
    const float* bout = (const float*)d_in[12];
    float* out = (float*)d_out;

    float *hA, *hB;
    cudaGetSymbolAddress((void**)&hA, g_hA);
    cudaGetSymbolAddress((void**)&hB, g_hB);

    int smCount = 148;
    cudaDeviceGetAttribute(&smCount, cudaDevAttrMultiProcessorCount, 0);

    int occPrep = 0;
    cudaOccupancyMaxActiveBlocksPerMultiprocessor(&occPrep, prep_kernel, 256, 0);
    if (occPrep < 1) occPrep = 1;
    int gridPrep = smCount * occPrep;    // co-resident -> barrier safe

    int occLayer = 0;
    cudaOccupancyMaxActiveBlocksPerMultiprocessor(&occLayer, layer_kernel<true>, 256, 0);
    if (occLayer < 1) occLayer = 1;
    int gridLayer = smCount * occLayer;  // co-resident -> barrier safe (LAST)

    // 1) CSR build + layer 1 in one persistent kernel
    prep_kernel<<<gridPrep, 256>>>(src, dst, gids, W1, b1);

    // 2-4) layers 2..4 (layer 4 fuses pooling + output head)
    layer_kernel<false><<<gridLayer, 256>>>(hA, hB, W2, b2, gids, Wout, bout, out);
    layer_kernel<false><<<gridLayer, 256>>>(hB, hA, W3, b3, gids, Wout, bout, out);
    layer_kernel<true ><<<gridLayer, 256>>>(hA, hB, W4, b4, gids, Wout, bout, out);
}

// round 14
// speedup vs baseline: 1.1593x; 1.1593x over previous
#include <cuda_runtime.h>
#include <cuda_fp16.h>
#include <cstdint>

#define NN 50000
#define EE 800000
#define GG 64
#define HH 64
#define NB ((NN + 255) / 256)   // 196 scan blocks

// ---------------- scratch (device globals; no allocation allowed) ----------
__device__ __align__(16) int    g_degin_i[NN];
__device__ __align__(16) int    g_degout_i[NN];
__device__ __align__(16) int    g_rowptr[NN + 1];
__device__ __align__(16) int    g_cursor[NN];
__device__ __align__(16) int    g_blocksum[NB];
__device__ __align__(16) int    g_csr_src[EE];
__device__ __align__(16) float  g_norm_src[NN];
__device__ __align__(16) float  g_norm_dst[NN];
__device__ __align__(16) float  g_h0[NN * 4];      // layer-1 input features (fp32, 4-wide)
__device__ __align__(16) __half g_hA[NN * HH];     // hidden ping buffer (fp16)
__device__ __align__(16) __half g_hB[NN * HH];     // hidden pong buffer (fp16)
__device__ __align__(16) float  g_agg1[NN * 4];    // layer-1 aggregation (fp32)
__device__ __align__(16) float  g_gsum[GG * HH];   // graph pooling sums (fp32)
__device__ __align__(16) float  g_gcnt[GG];

// ---------------- helpers ---------------------------------------------------
__device__ __forceinline__ void red4(float* p, float4 v) {
    asm volatile("red.global.add.v4.f32 [%0], {%1, %2, %3, %4};"
                 :: "l"(p), "f"(v.x), "f"(v.y), "f"(v.z), "f"(v.w) : "memory");
}

// ---------------- CSR build --------------------------------------------------
__global__ void init_kernel() {
    int i = blockIdx.x * blockDim.x + threadIdx.x;
    if (i < NN) { g_degin_i[i] = 0; g_degout_i[i] = 0; }
    if (i < GG * HH) g_gsum[i] = 0.f;
    if (i < GG) g_gcnt[i] = 0.f;
}

__global__ void deg_kernel(const int* __restrict__ src, const int* __restrict__ dst) {
    int e = blockIdx.x * blockDim.x + threadIdx.x;
    if (e >= EE) return;
    atomicAdd(&g_degin_i[dst[e]], 1);
    atomicAdd(&g_degout_i[src[e]], 1);
}

__global__ void scanA_kernel() {
    __shared__ int s[256];
    int t = threadIdx.x;
    int n = blockIdx.x * 256 + t;
    int v = (n < NN) ? g_degin_i[n] : 0;
    s[t] = v;
    __syncthreads();
#pragma unroll
    for (int off = 1; off < 256; off <<= 1) {
        int add = (t >= off) ? s[t - off] : 0;
        __syncthreads();
        s[t] += add;
        __syncthreads();
    }
    if (n < NN) g_rowptr[n] = s[t] - v;
    if (t == 255) g_blocksum[blockIdx.x] = s[255];
}

__global__ void scanB_kernel() {
    __shared__ int s[256];
    int t = threadIdx.x;
    int v = (t < NB) ? g_blocksum[t] : 0;
    s[t] = v;
    __syncthreads();
#pragma unroll
    for (int off = 1; off < 256; off <<= 1) {
        int add = (t >= off) ? s[t - off] : 0;
        __syncthreads();
        s[t] += add;
        __syncthreads();
    }
    if (t < NB) g_blocksum[t] = s[t] - v;
    if (t == 0) g_rowptr[NN] = EE;
}

__global__ void scanC_feats_kernel(const int* __restrict__ graph_ids) {
    int n = blockIdx.x * blockDim.x + threadIdx.x;
    if (n >= NN) return;
    int r = g_rowptr[n] + g_blocksum[n >> 8];
    g_rowptr[n] = r;
    g_cursor[n] = r;

    float di = (float)g_degin_i[n];
    float dout = (float)g_degout_i[n];
    float h1 = di;
    float h2 = (di - 3.f > 0.f) ? 1.f : 0.f;
    float h3 = 3.f / di;
    float h4 = (di - 4.f > 0.f) ? 1.f : 0.f;
    float ns = rsqrtf(fmaxf(dout, 1.f));
    float nd = rsqrtf(fmaxf(di, 1.f));
    g_norm_src[n] = ns;
    g_norm_dst[n] = nd;
    reinterpret_cast<float4*>(g_h0)[n] =
        make_float4(h1 * ns, h2 * ns, h3 * ns, h4 * ns);
    atomicAdd(&g_gcnt[graph_ids[n]], 1.f);
}

__global__ void scatter_kernel(const int* __restrict__ src, const int* __restrict__ dst) {
    int e = blockIdx.x * blockDim.x + threadIdx.x;
    if (e >= EE) return;
    int d = dst[e];
    int pos = atomicAdd(&g_cursor[d], 1);
    g_csr_src[pos] = src[e];
}

// ---------------- layer 1 (4-wide, fp32) --------------------------------------
__global__ void agg1_kernel() {
    int n = blockIdx.x * blockDim.x + threadIdx.x;
    if (n >= NN) return;
    int e0 = g_rowptr[n], e1 = g_rowptr[n + 1];
    const float4* h4 = reinterpret_cast<const float4*>(g_h0);
    float4 acc = make_float4(0.f, 0.f, 0.f, 0.f);
    int e = e0;
    for (; e + 1 < e1; e += 2) {
        float4 v0 = h4[g_csr_src[e]];
        float4 v1 = h4[g_csr_src[e + 1]];
        acc.x += v0.x + v1.x; acc.y += v0.y + v1.y;
        acc.z += v0.z + v1.z; acc.w += v0.w + v1.w;
    }
    if (e < e1) {
        float4 v = h4[g_csr_src[e]];
        acc.x += v.x; acc.y += v.y; acc.z += v.z; acc.w += v.w;
    }
    reinterpret_cast<float4*>(g_agg1)[n] = acc;
}

// writes layer-1 output (pre-scaled by norm_src) into g_hA as fp16
__global__ void node_first_kernel(const float* __restrict__ W1, const float* __restrict__ b1) {
    int t = blockIdx.x * blockDim.x + threadIdx.x;
    if (t >= NN * HH) return;
    int n = t >> 6;
    int o = t & 63;
    float nd = g_norm_dst[n];
    float ns = g_norm_src[n];
    float4 x = reinterpret_cast<const float4*>(g_agg1)[n];
    float acc = b1[o];
    acc = fmaf(x.x * nd, W1[0 * HH + o], acc);
    acc = fmaf(x.y * nd, W1[1 * HH + o], acc);
    acc = fmaf(x.z * nd, W1[2 * HH + o], acc);
    acc = fmaf(x.w * nd, W1[3 * HH + o], acc);
    acc = fmaxf(acc, 0.f) * ns;
    g_hA[t] = __float2half_rn(acc);
}

// ---------------- fused layers 2..4 (R8 champion structure, fp16 features) ----
// One warp = 4 nodes. Gather: fp16 rows (128B/node) -> one 8B load per lane per
// edge, fp32 accumulate. GEMM in fp32 from smem. Output stored fp16 (or fp32
// red4 pooling on LAST).
template <bool LAST>
__global__ void __launch_bounds__(256) layer_kernel(
        const __half* __restrict__ hin, __half* __restrict__ hout,
        const float* __restrict__ W, const float* __restrict__ b,
        const int* __restrict__ graph_ids) {
    __shared__ float Ws[HH * HH];
    __shared__ float bs[HH];
    __shared__ float xs[8][4][68];   // [warp][node-in-quad][64+pad]

    int tid = threadIdx.x;
    float4* Ws4 = reinterpret_cast<float4*>(Ws);
    const float4* Wg4 = reinterpret_cast<const float4*>(W);
    for (int i = tid; i < HH * HH / 4; i += 256) Ws4[i] = Wg4[i];
    if (tid < HH) bs[tid] = b[tid];
    __syncthreads();

    int warp = tid >> 5;
    int lane = tid & 31;
    int half_ = lane >> 4;     // 0 or 1
    int o4 = lane & 15;        // 8B slice index (4 features)

    const uint2* h2 = reinterpret_cast<const uint2*>(hin);  // row = 16 x 8B
    const int* __restrict__ csr = g_csr_src;

    const int NQ = NN / 4;     // 12500 quads

    for (int quad = blockIdx.x * 8 + warp; quad < NQ; quad += gridDim.x * 8) {
        // ---- gather: this lane handles nodes (half_) and (half_+2) of the quad
#pragma unroll
        for (int g = 0; g < 2; g++) {
            int q = half_ + 2 * g;
            int n = quad * 4 + q;
            int e0 = g_rowptr[n], e1 = g_rowptr[n + 1];
            float4 acc = make_float4(0.f, 0.f, 0.f, 0.f);
            int e = e0;
            for (; e + 3 < e1; e += 4) {
                int s0 = csr[e], s1 = csr[e + 1], s2 = csr[e + 2], s3 = csr[e + 3];
                uint2 u0 = h2[s0 * 16 + o4];
                uint2 u1 = h2[s1 * 16 + o4];
                uint2 u2 = h2[s2 * 16 + o4];
                uint2 u3 = h2[s3 * 16 + o4];
#pragma unroll
                for (int m = 0; m < 4; m++) {
                    uint2 u = (m == 0) ? u0 : (m == 1) ? u1 : (m == 2) ? u2 : u3;
                    float2 f0 = __half22float2(*reinterpret_cast<__half2*>(&u.x));
                    float2 f1 = __half22float2(*reinterpret_cast<__half2*>(&u.y));
                    acc.x += f0.x; acc.y += f0.y; acc.z += f1.x; acc.w += f1.y;
                }
            }
            for (; e < e1; e++) {
                uint2 u = h2[csr[e] * 16 + o4];
                float2 f0 = __half22float2(*reinterpret_cast<__half2*>(&u.x));
                float2 f1 = __half22float2(*reinterpret_cast<__half2*>(&u.y));
                acc.x += f0.x; acc.y += f0.y; acc.z += f1.x; acc.w += f1.y;
            }
            float nd = g_norm_dst[n];
            acc.x *= nd; acc.y *= nd; acc.z *= nd; acc.w *= nd;
            reinterpret_cast<float4*>(&xs[warp][q][0])[o4] = acc;
        }
        __syncwarp();
        // ---- GEMM: slice o4 for nodes q0=2*half_, q1=2*half_+1 (shared W loads)
        {
            int q0 = 2 * half_;
            int n0 = quad * 4 + q0;
            int n1 = n0 + 1;
            float4 bb = reinterpret_cast<float4*>(bs)[o4];
            float4 r0 = bb, r1 = bb;
            const float4* x0row = reinterpret_cast<const float4*>(&xs[warp][q0][0]);
            const float4* x1row = reinterpret_cast<const float4*>(&xs[warp][q0 + 1][0]);
#pragma unroll
            for (int k4 = 0; k4 < 16; k4++) {
                float4 x0v = x0row[k4];
                float4 x1v = x1row[k4];
#pragma unroll
                for (int j = 0; j < 4; j++) {
                    float4 w = Ws4[(k4 * 4 + j) * 16 + o4];
                    float a = (j == 0) ? x0v.x : (j == 1) ? x0v.y : (j == 2) ? x0v.z : x0v.w;
                    float c = (j == 0) ? x1v.x : (j == 1) ? x1v.y : (j == 2) ? x1v.z : x1v.w;
                    r0.x = fmaf(a, w.x, r0.x);
                    r0.y = fmaf(a, w.y, r0.y);
                    r0.z = fmaf(a, w.z, r0.z);
                    r0.w = fmaf(a, w.w, r0.w);
                    r1.x = fmaf(c, w.x, r1.x);
                    r1.y = fmaf(c, w.y, r1.y);
                    r1.z = fmaf(c, w.z, r1.z);
                    r1.w = fmaf(c, w.w, r1.w);
                }
            }
            r0.x = fmaxf(r0.x, 0.f); r0.y = fmaxf(r0.y, 0.f);
            r0.z = fmaxf(r0.z, 0.f); r0.w = fmaxf(r0.w, 0.f);
            r1.x = fmaxf(r1.x, 0.f); r1.y = fmaxf(r1.y, 0.f);
            r1.z = fmaxf(r1.z, 0.f); r1.w = fmaxf(r1.w, 0.f);
            if (!LAST) {
                float ns0 = g_norm_src[n0];
                float ns1 = g_norm_src[n1];
                r0.x *= ns0; r0.y *= ns0; r0.z *= ns0; r0.w *= ns0;
                r1.x *= ns1; r1.y *= ns1; r1.z *= ns1; r1.w *= ns1;
                __half2 a0 = __floats2half2_rn(r0.x, r0.y);
                __half2 a1 = __floats2half2_rn(r0.z, r0.w);
                __half2 c0 = __floats2half2_rn(r1.x, r1.y);
                __half2 c1 = __floats2half2_rn(r1.z, r1.w);
                uint2 s0, s1;
                s0.x = *reinterpret_cast<unsigned*>(&a0);
                s0.y = *reinterpret_cast<unsigned*>(&a1);
                s1.x = *reinterpret_cast<unsigned*>(&c0);
                s1.y = *reinterpret_cast<unsigned*>(&c1);
                reinterpret_cast<uint2*>(hout)[n0 * 16 + o4] = s0;
                reinterpret_cast<uint2*>(hout)[n1 * 16 + o4] = s1;
            } else {
                int g0 = graph_ids[n0];
                int g1 = graph_ids[n1];
                red4(&g_gsum[g0 * HH + o4 * 4], r0);
                red4(&g_gsum[g1 * HH + o4 * 4], r1);
            }
        }
        __syncwarp();
    }
}

// final head: per-graph mean, dot with Wout, + bout, sigmoid
__global__ void out_kernel(const float* __restrict__ Wout, const float* __restrict__ bout,
                           float* __restrict__ out) {
    __shared__ float s[HH];
    int g = blockIdx.x;
    int t = threadIdx.x;
    float inv = 1.f / g_gcnt[g];
    float v = g_gsum[g * HH + t] * inv * Wout[t];
    s[t] = v;
    __syncthreads();
    if (t < 32) {
        float x = s[t] + s[t + 32];
#pragma unroll
        for (int off = 16; off > 0; off >>= 1)
            x += __shfl_xor_sync(0xFFFFFFFF, x, off);
        if (t == 0) out[g] = 1.f / (1.f + expf(-(x + bout[0])));
    }
}

// ---------------- launch -----------------------------------------------------
extern "C" void kernel_launch(void* const* d_in, const int* in_sizes, int n_in,
                              void* d_out, int out_size) {
    const int*   src  = (const int*)d_in[0];
    const int*   dst  = (const int*)d_in[1];
    const int*   gids = (const int*)d_in[2];
    const float* W1   = (const float*)d_in[3];
    const float* b1   = (const float*)d_in[4];
    const float* W2   = (const float*)d_in[5];
    const float* b2   = (const float*)d_in[6];
    const float* W3   = (const float*)d_in[7];
    const float* b3   = (const float*)d_in[8];
    const float* W4   = (const float*)d_in[9];
    const float* b4   = (const float*)d_in[10];
    const float* Wout = (const float*)d_in[11];
    const float* bout = (const float*)d_in[12];
    float* out = (float*)d_out;

    __half *hA, *hB;
    cudaGetSymbolAddress((void**)&hA, g_hA);
    cudaGetSymbolAddress((void**)&hB, g_hB);

    const int T = 256;
    const int gridN  = (NN + T - 1) / T;
    const int gridE  = (EE + T - 1) / T;
    const int gridNH = (NN * HH + T - 1) / T;
    const int gridLayer = 888;

    // CSR build (once; reused for all 4 layers)
    init_kernel<<<gridN, T>>>();
    deg_kernel<<<gridE, T>>>(src, dst);
    scanA_kernel<<<NB, 256>>>();
    scanB_kernel<<<1, 256>>>();
    scanC_feats_kernel<<<gridN, T>>>(gids);
    scatter_kernel<<<gridE, T>>>(src, dst);

    // layer 1 (4-wide fp32): agg from g_h0, output (H-wide fp16) into hA
    agg1_kernel<<<gridN, T>>>();
    node_first_kernel<<<gridNH, T>>>(W1, b1);

    // layers 2..4 fused, double-buffered fp16: A->B, B->A, A->pool
    layer_kernel<false><<<gridLayer, T>>>(hA, hB, W2, b2, gids);
    layer_kernel<false><<<gridLayer, T>>>(hB, hA, W3, b3, gids);
    layer_kernel<true ><<<gridLayer, T>>>(hA, hB, W4, b4, gids);

    out_kernel<<<GG, HH>>>(Wout, bout, out);
}